// round 1
// baseline (speedup 1.0000x reference)
#include <cuda_runtime.h>
#include <cstddef>

#define NN 50000
#define EE 600000
#define DD 128
#define HH 128
#define LL 4
#define GG 256
#define CC 10
#define NBLK 196            // ceil(NN/256)
#define BN_EPS 1e-5f

// ---------------- device scratch (no runtime allocation allowed) ----------------
__device__ float g_z[(size_t)NN * HH];     // gather output z; reused as t2 (gemm2 out)
__device__ float g_t1[(size_t)NN * HH];    // gemm1 output
__device__ float g_h[(size_t)NN * HH];     // per-layer node features h
__device__ float g_pooled[GG * LL * HH];   // [G, L*H] pooled (concat layout)
__device__ float g_stats[4 * HH];          // sum1, sumsq1, sum2, sumsq2
__device__ float g_bn[4 * HH];             // scale1, shift1, scale2, shift2
__device__ int   g_deg[NN];
__device__ int   g_cursor[NN];
__device__ int   g_rowptr[NN + 1];
__device__ int   g_bsums[256];
__device__ int   g_colsrc[EE];

// ---------------- utility ----------------
__global__ void zero_f_kernel(float* p, int n) {
    for (int i = blockIdx.x * blockDim.x + threadIdx.x; i < n; i += gridDim.x * blockDim.x)
        p[i] = 0.f;
}
__global__ void zero_i_kernel(int* p, int n) {
    for (int i = blockIdx.x * blockDim.x + threadIdx.x; i < n; i += gridDim.x * blockDim.x)
        p[i] = 0;
}

// ---------------- CSR build (by dst) ----------------
__global__ void hist_kernel(const int* __restrict__ dst) {
    int e = blockIdx.x * blockDim.x + threadIdx.x;
    if (e < EE) atomicAdd(&g_deg[dst[e]], 1);
}

__global__ void scan1_kernel() {
    __shared__ int sh[256];
    int tid = threadIdx.x;
    int i = blockIdx.x * 256 + tid;
    int v = (i < NN) ? g_deg[i] : 0;
    sh[tid] = v;
    __syncthreads();
    #pragma unroll
    for (int off = 1; off < 256; off <<= 1) {
        int t = (tid >= off) ? sh[tid - off] : 0;
        __syncthreads();
        sh[tid] += t;
        __syncthreads();
    }
    if (i < NN) g_rowptr[i] = sh[tid] - v;   // exclusive within block
    if (tid == 255) g_bsums[blockIdx.x] = sh[255];
}

__global__ void scan2_kernel(int nb) {
    __shared__ int sh[256];
    int tid = threadIdx.x;
    int v = (tid < nb) ? g_bsums[tid] : 0;
    sh[tid] = v;
    __syncthreads();
    #pragma unroll
    for (int off = 1; off < 256; off <<= 1) {
        int t = (tid >= off) ? sh[tid - off] : 0;
        __syncthreads();
        sh[tid] += t;
        __syncthreads();
    }
    if (tid < nb) g_bsums[tid] = sh[tid] - v;  // exclusive block offsets
}

__global__ void scan3_kernel() {
    int i = blockIdx.x * 256 + threadIdx.x;
    if (i < NN) {
        int r = g_rowptr[i] + g_bsums[blockIdx.x];
        g_rowptr[i] = r;
        g_cursor[i] = r;
    }
    if (i == 0) g_rowptr[NN] = EE;
}

__global__ void fill_kernel(const int* __restrict__ src, const int* __restrict__ dst) {
    int e = blockIdx.x * blockDim.x + threadIdx.x;
    if (e < EE) {
        int d = dst[e];
        int p = atomicAdd(&g_cursor[d], 1);
        g_colsrc[p] = src[e];
    }
}

// ---------------- gather: z[n] = (1+eps)*h[n] + sum_{j->n} h[src_j] ----------------
__global__ __launch_bounds__(256) void gather_kernel(
    const float* __restrict__ h, const float* __restrict__ eps, int layer)
{
    int warp = (blockIdx.x * blockDim.x + threadIdx.x) >> 5;
    if (warp >= NN) return;
    int lane = threadIdx.x & 31;
    float epi = 1.0f + __ldg(&eps[layer]);
    const float4* hp = reinterpret_cast<const float4*>(h);
    float4 v = __ldg(&hp[(size_t)warp * 32 + lane]);
    float4 acc = make_float4(v.x * epi, v.y * epi, v.z * epi, v.w * epi);
    int s = g_rowptr[warp];
    int e = g_rowptr[warp + 1];
    for (int j = s; j < e; j++) {
        int sn = __ldg(&g_colsrc[j]);
        float4 u = __ldg(&hp[(size_t)sn * 32 + lane]);
        acc.x += u.x; acc.y += u.y; acc.z += u.z; acc.w += u.w;
    }
    reinterpret_cast<float4*>(g_z)[(size_t)warp * 32 + lane] = acc;
}

// ---------------- SGEMM: C = xf(A) @ W + bias ; also accumulates column sum/sumsq ----
// 128x128 tile, 256 threads, 8x8 microtile. Optional A transform = ReLU(BN) via scale/shift.
template <bool XFORM>
__global__ __launch_bounds__(256, 2) void gemm_kernel(
    const float* __restrict__ A, const float* __restrict__ W,
    const float* __restrict__ bias, float* __restrict__ Cout,
    float* __restrict__ stats,
    const float* __restrict__ bnscale, const float* __restrict__ bnshift)
{
    __shared__ float As[16][128];   // [k][m]
    __shared__ float Bs[16][128];   // [k][n]
    __shared__ float s_red[2][128];

    const int t = threadIdx.x;
    const int rowBase = blockIdx.x * 128;
    const int tx = t & 15;
    const int ty = t >> 4;
    const int m0 = ty * 8;
    const int n0 = tx * 8;

    if (t < 128) { s_red[0][t] = 0.f; s_red[1][t] = 0.f; }

    float acc[8][8];
    #pragma unroll
    for (int i = 0; i < 8; i++)
        #pragma unroll
        for (int j = 0; j < 8; j++) acc[i][j] = 0.f;

    for (int k0 = 0; k0 < 128; k0 += 16) {
        #pragma unroll
        for (int i = 0; i < 2; i++) {
            int f = t * 2 + i;               // 0..511
            int m = f >> 2;
            int kk = (f & 3) * 4;
            int row = rowBase + m;
            float4 v = make_float4(0.f, 0.f, 0.f, 0.f);
            if (row < NN)
                v = *reinterpret_cast<const float4*>(&A[(size_t)row * 128 + k0 + kk]);
            if (XFORM) {
                v.x = fmaxf(fmaf(v.x, bnscale[k0 + kk + 0], bnshift[k0 + kk + 0]), 0.f);
                v.y = fmaxf(fmaf(v.y, bnscale[k0 + kk + 1], bnshift[k0 + kk + 1]), 0.f);
                v.z = fmaxf(fmaf(v.z, bnscale[k0 + kk + 2], bnshift[k0 + kk + 2]), 0.f);
                v.w = fmaxf(fmaf(v.w, bnscale[k0 + kk + 3], bnshift[k0 + kk + 3]), 0.f);
            }
            As[kk + 0][m] = v.x;
            As[kk + 1][m] = v.y;
            As[kk + 2][m] = v.z;
            As[kk + 3][m] = v.w;
        }
        #pragma unroll
        for (int i = 0; i < 2; i++) {
            int f = t * 2 + i;
            int kk = f >> 5;
            int c = (f & 31) * 4;
            *reinterpret_cast<float4*>(&Bs[kk][c]) =
                *reinterpret_cast<const float4*>(&W[(size_t)(k0 + kk) * 128 + c]);
        }
        __syncthreads();
        #pragma unroll
        for (int kk = 0; kk < 16; kk++) {
            float a[8], b[8];
            *reinterpret_cast<float4*>(&a[0]) = *reinterpret_cast<const float4*>(&As[kk][m0]);
            *reinterpret_cast<float4*>(&a[4]) = *reinterpret_cast<const float4*>(&As[kk][m0 + 4]);
            *reinterpret_cast<float4*>(&b[0]) = *reinterpret_cast<const float4*>(&Bs[kk][n0]);
            *reinterpret_cast<float4*>(&b[4]) = *reinterpret_cast<const float4*>(&Bs[kk][n0 + 4]);
            #pragma unroll
            for (int i = 0; i < 8; i++)
                #pragma unroll
                for (int j = 0; j < 8; j++)
                    acc[i][j] = fmaf(a[i], b[j], acc[i][j]);
        }
        __syncthreads();
    }

    float bb[8];
    *reinterpret_cast<float4*>(&bb[0]) = *reinterpret_cast<const float4*>(&bias[n0]);
    *reinterpret_cast<float4*>(&bb[4]) = *reinterpret_cast<const float4*>(&bias[n0 + 4]);

    float csum[8], csq[8];
    #pragma unroll
    for (int j = 0; j < 8; j++) { csum[j] = 0.f; csq[j] = 0.f; }

    #pragma unroll
    for (int i = 0; i < 8; i++) {
        int row = rowBase + m0 + i;
        if (row < NN) {
            float o[8];
            #pragma unroll
            for (int j = 0; j < 8; j++) {
                float v = acc[i][j] + bb[j];
                o[j] = v;
                csum[j] += v;
                csq[j] = fmaf(v, v, csq[j]);
            }
            *reinterpret_cast<float4*>(&Cout[(size_t)row * 128 + n0]) =
                *reinterpret_cast<float4*>(&o[0]);
            *reinterpret_cast<float4*>(&Cout[(size_t)row * 128 + n0 + 4]) =
                *reinterpret_cast<float4*>(&o[4]);
        }
    }
    #pragma unroll
    for (int j = 0; j < 8; j++) {
        atomicAdd(&s_red[0][n0 + j], csum[j]);
        atomicAdd(&s_red[1][n0 + j], csq[j]);
    }
    __syncthreads();
    if (t < 128) {
        atomicAdd(&stats[t], s_red[0][t]);
        atomicAdd(&stats[128 + t], s_red[1][t]);
    }
}

// ---------------- BN finalize: stats -> (scale, shift) ----------------
__global__ void finalize_kernel(const float* __restrict__ stats,
                                const float* __restrict__ gamma,
                                const float* __restrict__ beta,
                                float* __restrict__ scale,
                                float* __restrict__ shift)
{
    int c = threadIdx.x;  // 128
    float inv = 1.0f / (float)NN;
    float mean = stats[c] * inv;
    float var = stats[128 + c] * inv - mean * mean;
    float rs = rsqrtf(var + BN_EPS);
    float sc = rs * gamma[c];
    scale[c] = sc;
    shift[c] = beta[c] - mean * sc;
}

// ---------------- finish: h = relu(bn2(t2)); pooled += segment_sum(h, batch) -----
__global__ __launch_bounds__(128) void finish_kernel(
    const float* __restrict__ t2, const float* __restrict__ scale,
    const float* __restrict__ shift, const int* __restrict__ batch, int layer)
{
    int c = threadIdx.x;                   // 0..127
    int r0 = blockIdx.x * 128;
    int rend = min(r0 + 128, NN);
    float sc = scale[c], sh = shift[c];
    float acc = 0.f;
    int curg = -1;
    for (int r = r0; r < rend; r++) {
        float v = fmaxf(fmaf(t2[(size_t)r * 128 + c], sc, sh), 0.f);
        g_h[(size_t)r * 128 + c] = v;
        int g = __ldg(&batch[r]);
        if (g != curg) {
            if (curg >= 0) atomicAdd(&g_pooled[(size_t)curg * (LL * HH) + layer * HH + c], acc);
            curg = g;
            acc = 0.f;
        }
        acc += v;
    }
    if (curg >= 0) atomicAdd(&g_pooled[(size_t)curg * (LL * HH) + layer * HH + c], acc);
}

// ---------------- head: out = relu(pooled @ fc1 + b) @ fc2 + b ----------------
__global__ __launch_bounds__(128) void head_kernel(
    const float* __restrict__ fc1w, const float* __restrict__ fc1b,
    const float* __restrict__ fc2w, const float* __restrict__ fc2b,
    float* __restrict__ out)
{
    __shared__ float p[LL * HH];
    __shared__ float q[HH];
    int g = blockIdx.x;
    int t = threadIdx.x;    // 128
    #pragma unroll
    for (int i = t; i < LL * HH; i += 128) p[i] = g_pooled[(size_t)g * (LL * HH) + i];
    __syncthreads();
    float acc = fc1b[t];
    #pragma unroll 8
    for (int k = 0; k < LL * HH; k++) acc = fmaf(p[k], __ldg(&fc1w[(size_t)k * HH + t]), acc);
    q[t] = fmaxf(acc, 0.f);
    __syncthreads();
    if (t < CC) {
        float o = fc2b[t];
        #pragma unroll 8
        for (int k = 0; k < HH; k++) o = fmaf(q[k], __ldg(&fc2w[(size_t)k * CC + t]), o);
        out[(size_t)g * CC + t] = o;
    }
}

// ---------------- host launch ----------------
extern "C" void kernel_launch(void* const* d_in, const int* in_sizes, int n_in,
                              void* d_out, int out_size)
{
    const float* x     = (const float*)d_in[0];
    const int*   ei    = (const int*)d_in[1];
    const int*   batch = (const int*)d_in[2];
    const float* W1    = (const float*)d_in[3];
    const float* b1    = (const float*)d_in[4];
    const float* g1    = (const float*)d_in[5];
    const float* bt1   = (const float*)d_in[6];
    const float* W2    = (const float*)d_in[7];
    const float* b2    = (const float*)d_in[8];
    const float* g2    = (const float*)d_in[9];
    const float* bt2   = (const float*)d_in[10];
    const float* eps   = (const float*)d_in[11];
    const float* fc1w  = (const float*)d_in[12];
    const float* fc1b  = (const float*)d_in[13];
    const float* fc2w  = (const float*)d_in[14];
    const float* fc2b  = (const float*)d_in[15];
    float* out = (float*)d_out;

    const int* src = ei;
    const int* dst = ei + EE;

    float *z, *t1, *h, *pooled, *stats, *bn;
    int *deg;
    cudaGetSymbolAddress((void**)&z, g_z);
    cudaGetSymbolAddress((void**)&t1, g_t1);
    cudaGetSymbolAddress((void**)&h, g_h);
    cudaGetSymbolAddress((void**)&pooled, g_pooled);
    cudaGetSymbolAddress((void**)&stats, g_stats);
    cudaGetSymbolAddress((void**)&bn, g_bn);
    cudaGetSymbolAddress((void**)&deg, g_deg);

    // ---- CSR build (once per launch; edges fixed) ----
    zero_i_kernel<<<128, 256>>>(deg, NN);
    hist_kernel<<<(EE + 255) / 256, 256>>>(dst);
    scan1_kernel<<<NBLK, 256>>>();
    scan2_kernel<<<1, 256>>>(NBLK);
    scan3_kernel<<<NBLK, 256>>>();
    fill_kernel<<<(EE + 255) / 256, 256>>>(src, dst);

    zero_f_kernel<<<128, 256>>>(pooled, GG * LL * HH);

    const float* hcur = x;
    const int gemm_blocks = (NN + 127) / 128;  // 391
    for (int i = 0; i < LL; i++) {
        zero_f_kernel<<<2, 256>>>(stats, 4 * HH);
        gather_kernel<<<(NN * 32 + 255) / 256, 256>>>(hcur, eps, i);
        // t1 = z @ W1[i] + b1[i]; stats1
        gemm_kernel<false><<<gemm_blocks, 256>>>(
            z, W1 + (size_t)i * DD * HH, b1 + (size_t)i * HH, t1,
            stats, nullptr, nullptr);
        finalize_kernel<<<1, 128>>>(stats, g1 + (size_t)i * HH, bt1 + (size_t)i * HH,
                                    bn, bn + 128);
        // t2 (into z) = relu(bn1(t1)) @ W2[i] + b2[i]; stats2
        gemm_kernel<true><<<gemm_blocks, 256>>>(
            t1, W2 + (size_t)i * HH * HH, b2 + (size_t)i * HH, z,
            stats + 256, bn, bn + 128);
        finalize_kernel<<<1, 128>>>(stats + 256, g2 + (size_t)i * HH, bt2 + (size_t)i * HH,
                                    bn + 256, bn + 384);
        // h = relu(bn2(t2)); pooled += segsum(h)
        finish_kernel<<<gemm_blocks, 128>>>(z, bn + 256, bn + 384, batch, i);
        hcur = h;
    }

    head_kernel<<<GG, 128>>>(fc1w, fc1b, fc2w, fc2b, out);
}